// round 11
// baseline (speedup 1.0000x reference)
#include <cuda_runtime.h>
#include <cstdint>

#define BB 8
#define CC 512
#define NNODES 2048
#define TT 24

#define K1_PITCH 192                       // words per c-row (768 B)
#define K1_TILE  (128*K1_PITCH)            // words per buffer
#define K1_SMEM  ((2*K1_TILE + 256) * 4)   // two buffers + w2 slice + f1 stage (bytes)

typedef unsigned long long ull;

// ---------------- scratch (static device arrays; no allocation) ----------------
__device__ float g_f1  [BB*TT*NNODES];   // f1[b][t][n]          (atomically accumulated)
__device__ float g_f1c [BB*TT*NNODES];   // dilated conv of f1
__device__ float g_f2  [BB*CC*TT];       // f2[b][c][t]          (atomically accumulated)
__device__ float g_f2cT[BB*TT*CC];       // f2c transposed [b][t][c]   (atomically accumulated)
__device__ float g_g   [BB*TT*CC];       // g[b][t][c] = f1c @ w       (atomically accumulated)
__device__ float g_s   [BB*TT*TT];       // sigmoid attention matrix

// ---------------- packed f32x2 helpers ----------------
__device__ __forceinline__ ull fma2(ull a, ull b, ull c){
    ull d;
    asm("fma.rn.f32x2 %0, %1, %2, %3;" : "=l"(d) : "l"(a), "l"(b), "l"(c));
    return d;
}
__device__ __forceinline__ ull add2(ull a, ull b){
    ull d;
    asm("add.rn.f32x2 %0, %1, %2;" : "=l"(d) : "l"(a), "l"(b));
    return d;
}
__device__ __forceinline__ ull pack2(float f){
    ull r;
    asm("mov.b64 %0, {%1, %1};" : "=l"(r) : "f"(f));
    return r;
}
__device__ __forceinline__ float2 unpk2(ull v){
    float2 f;
    asm("mov.b64 {%0, %1}, %2;" : "=f"(f.x), "=f"(f.y) : "l"(v));
    return f;
}

// ---------------- K0: zero accumulated scratch ----------------
__global__ void k0_zero(){
    int idx = blockIdx.x * 256 + threadIdx.x;
    if (idx < BB*TT*NNODES) g_f1[idx] = 0.0f;
    if (idx < BB*CC*TT){
        g_f2  [idx] = 0.0f;
        g_f2cT[idx] = 0.0f;
        g_g   [idx] = 0.0f;
    }
}

// ---------------- K1: fused dual weighted reduction over seq ----------------
// grid = 8b x 4ct x 32ns = 1024 blocks, block = 192, 1 block/SM.
// cp.async double-buffered chunks of (128c x 8n x 24t); XOR-swizzled smem tile.
// SINGLE compute pass: each LDS.128 feeds both f2 (register acc) and f1
// (butterfly-reduced over the 32 c-lanes), halving crossbar read traffic.
__device__ __forceinline__ void k1_stage(const float* gbase, float* buf, int ju, int c0s){
#pragma unroll
    for (int k2 = 0; k2 < 32; ++k2){
        const int c = c0s + 4*k2;
        const float* g = gbase + (size_t)c * (NNODES*TT);
        unsigned sa = (unsigned)__cvta_generic_to_shared(
            &buf[c*K1_PITCH + ((ju ^ (c & 7)) << 2)]);
        asm volatile("cp.async.cg.shared.global [%0], [%1], 16;" :: "r"(sa), "l"(g) : "memory");
    }
    asm volatile("cp.async.commit_group;" ::: "memory");
}

__global__ void __launch_bounds__(192, 1)
k1_reduce(const float* __restrict__ seq, const float* __restrict__ w1, const float* __restrict__ w2){
    extern __shared__ float sm[];
    float* buf0 = sm;
    float* buf1 = sm + K1_TILE;
    float* sw2n = sm + 2*K1_TILE;      // [64]
    float* f1st = sw2n + 64;           // [8 nn][24 t]

    const int blk = blockIdx.x;
    const int b   = blk >> 7;          // 0..7
    const int ct  = (blk >> 5) & 3;    // c-tile 0..3
    const int ns  = blk & 31;          // n-sweep 0..31 (64 n each)
    const int nb  = ns * 64;
    const int tid = threadIdx.x;
    const int w   = tid >> 5;          // warp -> t-quad
    const int lane= tid & 31;
    const int ju  = tid % 48;          // float4 unit within c-row segment
    const int c0s = tid / 48;          // 0..3

    if (tid < 64) sw2n[tid] = w2[nb + tid];

    const float* seqbase = seq + ((size_t)(b*CC + ct*128) * NNODES + nb) * TT + ju*4;

    ull w1p[4];
#pragma unroll
    for (int kk = 0; kk < 4; ++kk) w1p[kk] = pack2(w1[ct*128 + lane + 32*kk]);

    ull acc[4][2];
#pragma unroll
    for (int kk = 0; kk < 4; ++kk){ acc[kk][0] = 0ull; acc[kk][1] = 0ull; }

    const int xm = lane & 7;

    k1_stage(seqbase, buf0, ju, c0s);

    for (int ch = 0; ch < 8; ++ch){
        float* cur = (ch & 1) ? buf1 : buf0;
        if (ch < 7){
            k1_stage(seqbase + (size_t)(ch+1)*8*TT, (ch & 1) ? buf0 : buf1, ju, c0s);
            asm volatile("cp.async.wait_group 1;" ::: "memory");
        } else {
            asm volatile("cp.async.wait_group 0;" ::: "memory");
        }
        __syncthreads();   // sync(A): buffer ready; prior flush reads complete

        // ---- fused compute: one LDS.128 feeds both reductions ----
#pragma unroll
        for (int nn = 0; nn < 8; ++nn){
            const ull w2p = pack2(sw2n[ch*8 + nn]);
            const int u = 6*nn + w;
            const int so = ((u ^ xm) << 2);
            ull p0 = 0ull, p1 = 0ull;
#pragma unroll
            for (int kk = 0; kk < 4; ++kk){
                const ulonglong2 x = *reinterpret_cast<const ulonglong2*>(
                    &cur[(lane + 32*kk)*K1_PITCH + so]);
                acc[kk][0] = fma2(w2p, x.x, acc[kk][0]);
                acc[kk][1] = fma2(w2p, x.y, acc[kk][1]);
                p0 = fma2(w1p[kk], x.x, p0);
                p1 = fma2(w1p[kk], x.y, p1);
            }
#pragma unroll
            for (int off = 16; off > 0; off >>= 1){
                p0 = add2(p0, __shfl_xor_sync(0xffffffffu, p0, off));
                p1 = add2(p1, __shfl_xor_sync(0xffffffffu, p1, off));
            }
            if (lane == 0){
                float2 a = unpk2(p0), d = unpk2(p1);
                *reinterpret_cast<float4*>(&f1st[nn*24 + w*4]) = make_float4(a.x, a.y, d.x, d.y);
            }
        }
        __syncthreads();   // sync(B): f1st complete

        // ---- flush f1 partial (192 floats, one per thread, coalesced in n) ----
        {
            const int nn = tid / 24, t = tid - nn*24;
            atomicAdd(&g_f1[((size_t)b*TT + t)*NNODES + nb + ch*8 + nn], f1st[nn*24 + t]);
        }
        // next iteration's sync(A) orders these reads before f1st is rewritten
    }

    // ---- flush f2 (register-resident across the 64-n sweep) ----
#pragma unroll
    for (int kk = 0; kk < 4; ++kk){
        const int c = ct*128 + lane + 32*kk;
        float* o = g_f2 + ((size_t)b*CC + c)*TT + w*4;
        float2 a = unpk2(acc[kk][0]), d = unpk2(acc[kk][1]);
        atomicAdd(o + 0, a.x);
        atomicAdd(o + 1, a.y);
        atomicAdd(o + 2, d.x);
        atomicAdd(o + 3, d.y);
    }
}

// ---------------- K2a: dilated conv of f1 over the n axis ----------------
__global__ void k2a_conv1(const float* __restrict__ Wd1){
    const int b  = blockIdx.x >> 4;
    const int n0 = (blockIdx.x & 15) * 128;
    __shared__ float s1[TT][130];
    __shared__ float sw[TT][48];
    for (int idx = threadIdx.x; idx < TT*48; idx += 256)
        ((float*)sw)[idx] = Wd1[idx];
    for (int idx = threadIdx.x; idx < TT*130; idx += 256){
        int i = idx / 130, jj = idx % 130;
        int n = n0 + jj - 1;
        s1[i][jj] = (n >= 0 && n < NNODES) ? g_f1[((size_t)b*TT + i)*NNODES + n] : 0.0f;
    }
    __syncthreads();
#pragma unroll
    for (int u = 0; u < 12; ++u){
        int idx = threadIdx.x + u*256;
        int t = idx >> 7, nl = idx & 127;
        float acc = 0.0f;
#pragma unroll
        for (int i = 0; i < TT; ++i)
            acc += s1[i][nl] * sw[t][2*i] + s1[i][nl+2] * sw[t][2*i+1];
        g_f1c[((size_t)b*TT + t)*NNODES + n0 + nl] = acc;
    }
}

// ---------------- K2b: dilated conv of f2 over the t axis (K-split GEMM) ----------------
__global__ void __launch_bounds__(256) k2b_conv2(const float* __restrict__ Wd2){
    const int o0 = (blockIdx.x & 15) * 32;
    const int i0 = (blockIdx.x >> 4) * 32;
    const int tid   = threadIdx.x;
    const int olane = tid & 31;
    const int b     = tid >> 5;

    __shared__ __align__(16) float  sf[32][8][26];
    __shared__ float2 sw2[32][33];

    {
        int i = tid >> 3, bb = tid & 7;
        sf[i][bb][0] = 0.0f; sf[i][bb][25] = 0.0f;
    }
#pragma unroll
    for (int u = 0; u < 24; ++u){
        int idx = tid + u*256;
        int i = idx / 192, r = idx % 192;
        int bb = r / 24, t = r % 24;
        sf[i][bb][t+1] = g_f2[((size_t)bb*CC + i0 + i)*TT + t];
    }
    const float2* wsrc = reinterpret_cast<const float2*>(Wd2);
#pragma unroll
    for (int u = 0; u < 4; ++u){
        int idx = tid + u*256;
        int oo = idx >> 5, iz = idx & 31;
        sw2[oo][iz] = wsrc[(size_t)(o0+oo)*CC + i0 + iz];
    }
    __syncthreads();

    ull acc[12];
#pragma unroll
    for (int u = 0; u < 12; ++u) acc[u] = 0ull;
#pragma unroll 4
    for (int iz = 0; iz < 32; ++iz){
        float2 wv = sw2[olane][iz];
        ull wx = pack2(wv.x), wy = pack2(wv.y);
        const ull* R = reinterpret_cast<const ull*>(&sf[iz][b][0]);
#pragma unroll
        for (int u = 0; u < 12; ++u){
            acc[u] = fma2(wx, R[u], acc[u]);
            acc[u] = fma2(wy, R[u+1], acc[u]);
        }
    }
    float* ob = g_f2cT + (size_t)b*TT*CC + o0 + olane;
#pragma unroll
    for (int u = 0; u < 12; ++u){
        float2 r = unpk2(acc[u]);
        atomicAdd(&ob[(2*u  )*CC], r.x);
        atomicAdd(&ob[(2*u+1)*CC], r.y);
    }
}

// ---------------- K2c: g[b,t,c] += sum_n f1c[b,t,n] * w[n,c]  (K-split x4) ----------------
__global__ void __launch_bounds__(192) k2c_gemm(const float* __restrict__ w){
    const int b  = blockIdx.x >> 6;
    const int c0 = ((blockIdx.x >> 2) & 15) * 32;
    const int ks = blockIdx.x & 3;
    const int tid = threadIdx.x;
    const int tq = tid >> 3;
    const int cq = tid & 7;
    __shared__ __align__(16) float sA[TT*129];
    __shared__ __align__(16) float sB[128*36];
    ull acc[2] = {0ull, 0ull};
    for (int kt = 0; kt < 4; ++kt){
        const int n0 = ks*512 + kt*128;
        for (int idx = tid; idx < 3072; idx += 192){
            int r = idx >> 7, col = idx & 127;
            sA[r*129 + col] = g_f1c[((size_t)b*TT + r)*NNODES + n0 + col];
        }
        for (int idx = tid; idx < 4096; idx += 192){
            int r = idx >> 5, cl = idx & 31;
            sB[r*36 + cl] = w[(size_t)(n0 + r)*CC + c0 + cl];
        }
        __syncthreads();
#pragma unroll 8
        for (int r = 0; r < 128; ++r){
            ull a0 = pack2(sA[tq*129 + r]);
            ulonglong2 bv = *reinterpret_cast<const ulonglong2*>(&sB[r*36 + cq*4]);
            acc[0] = fma2(a0, bv.x, acc[0]);
            acc[1] = fma2(a0, bv.y, acc[1]);
        }
        __syncthreads();
    }
    float2 r0 = unpk2(acc[0]), r1 = unpk2(acc[1]);
    float* o0 = g_g + ((size_t)b*TT + tq)*CC + c0 + cq*4;
    atomicAdd(&o0[0], r0.x);
    atomicAdd(&o0[1], r0.y);
    atomicAdd(&o0[2], r1.x);
    atomicAdd(&o0[3], r1.y);
}

// ---------------- K2d1: s[b,j,k] = sigmoid(g[b,j,:] . f2cT[b,k,:] + bias) ----------------
__global__ void __launch_bounds__(128) k2d1_attn(const float* __restrict__ bbias){
    const int b = blockIdx.x / 24;
    const int jj = blockIdx.x % 24;
    const int tid  = threadIdx.x;
    const int wrp  = tid >> 5;
    const int lane = tid & 31;
    __shared__ __align__(16) float sg[CC];
    const float* grow = g_g + ((size_t)b*TT + jj)*CC;
#pragma unroll
    for (int u = 0; u < 4; ++u) sg[tid + u*128] = grow[tid + u*128];
    __syncthreads();
    const ull* sg2 = reinterpret_cast<const ull*>(sg);
    const ull* f0  = reinterpret_cast<const ull*>(g_f2cT + ((size_t)b*TT + wrp*6)*CC);
    ull acc[6] = {0ull,0ull,0ull,0ull,0ull,0ull};
#pragma unroll
    for (int it = 0; it < 8; ++it){
        ull gv = sg2[lane + it*32];
#pragma unroll
        for (int kk = 0; kk < 6; ++kk)
            acc[kk] = fma2(f0[(size_t)kk*256 + lane + it*32], gv, acc[kk]);
    }
#pragma unroll
    for (int kk = 0; kk < 6; ++kk)
#pragma unroll
        for (int off = 16; off > 0; off >>= 1)
            acc[kk] = add2(acc[kk], __shfl_xor_sync(0xffffffffu, acc[kk], off));
    if (lane < 6){
        int k = wrp*6 + lane;
        float2 aa = unpk2(acc[lane]);
        float sv = aa.x + aa.y + bbias[jj*TT + k];
        g_s[((size_t)b*TT + jj)*TT + k] = 1.0f/(1.0f + __expf(-sv));
    }
}

// ---------------- K2d2: l = v @ s; BN + mask + softmax (single block) ----------------
__global__ void k2d2_final(const float* __restrict__ v, const float* __restrict__ gamma,
                           const float* __restrict__ beta, float* __restrict__ out){
    const int tid = threadIdx.x;
    __shared__ float ss[BB][TT][TT];
    __shared__ float sv[TT][TT];
    __shared__ float sl[192][25];
    __shared__ float smean[TT], sinv[TT];
    for (int idx = tid; idx < BB*TT*TT; idx += 192) ((float*)ss)[idx] = g_s[idx];
    for (int idx = tid; idx < TT*TT;   idx += 192) ((float*)sv)[idx] = v[idx];
    __syncthreads();
    const int b = tid / TT, i = tid % TT;
    float l[TT];
#pragma unroll
    for (int k = 0; k < TT; ++k) l[k] = 0.0f;
#pragma unroll
    for (int jj = 0; jj < TT; ++jj){
        float vij = sv[i][jj];
#pragma unroll
        for (int k = 0; k < TT; ++k) l[k] = fmaf(vij, ss[b][jj][k], l[k]);
    }
#pragma unroll
    for (int k = 0; k < TT; ++k) sl[tid][k] = l[k];
    __syncthreads();
    if (tid < TT){
        float s = 0.0f, s2 = 0.0f;
        for (int r = 0; r < 192; ++r){ float x = sl[r][tid]; s += x; s2 = fmaf(x, x, s2); }
        float m = s * (1.0f/192.0f);
        smean[tid] = m;
        sinv[tid]  = rsqrtf(s2 * (1.0f/192.0f) - m*m + 1e-5f);
    }
    __syncthreads();
    float mx = -3.4e38f;
#pragma unroll
    for (int k = 0; k < TT; ++k){
        float y = (l[k] - smean[k]) * sinv[k] * gamma[k] + beta[k];
        if ((i < 12) != (k < 12)) y -= 1e13f;
        l[k] = y;
        mx = fmaxf(mx, y);
    }
    float s = 0.0f;
#pragma unroll
    for (int k = 0; k < TT; ++k){ float e = __expf(l[k] - mx); l[k] = e; s += e; }
    float inv = 1.0f / s;
#pragma unroll
    for (int k = 0; k < TT; ++k)
        out[((size_t)b*TT + i)*TT + k] = l[k] * inv;
}

// ---------------- launch ----------------
extern "C" void kernel_launch(void* const* d_in, const int* in_sizes, int n_in,
                              void* d_out, int out_size){
    const float* seq   = (const float*)d_in[0];
    const float* w1    = (const float*)d_in[1];
    const float* w2    = (const float*)d_in[2];
    const float* Wd1   = (const float*)d_in[3];
    const float* Wd2   = (const float*)d_in[4];
    const float* w     = (const float*)d_in[5];
    const float* bbias = (const float*)d_in[6];
    const float* v     = (const float*)d_in[7];
    const float* gamma = (const float*)d_in[8];
    const float* beta  = (const float*)d_in[9];
    float* out = (float*)d_out;

    cudaFuncSetAttribute(k1_reduce, cudaFuncAttributeMaxDynamicSharedMemorySize, K1_SMEM);

    k0_zero   <<<(BB*TT*NNODES + 255)/256, 256>>>();
    k1_reduce <<<1024, 192, K1_SMEM>>>(seq, w1, w2);
    k2a_conv1 <<<BB*16, 256>>>(Wd1);
    k2b_conv2 <<<256, 256>>>(Wd2);
    k2c_gemm  <<<512, 192>>>(w);
    k2d1_attn <<<BB*TT, 128>>>(bbias);
    k2d2_final<<<1, 192>>>(v, gamma, beta, out);
}

// round 12
// speedup vs baseline: 1.0091x; 1.0091x over previous
#include <cuda_runtime.h>
#include <cstdint>

#define BB 8
#define CC 512
#define NNODES 2048
#define TT 24

#define K1_NC    4                          // n per chunk
#define K1_PITCH 96                         // words per c-row segment (4n*24t)
#define K1_TILE  (128*K1_PITCH)             // words per buffer (48 KB)
#define K1_SMEM  ((2*K1_TILE + 160) * 4)    // two buffers + w2 slice + f1 stage

typedef unsigned long long ull;

// ---------------- scratch (static device arrays; no allocation) ----------------
__device__ float g_f1  [BB*TT*NNODES];   // f1[b][t][n]          (atomically accumulated)
__device__ float g_f1c [BB*TT*NNODES];   // dilated conv of f1
__device__ float g_f2  [BB*CC*TT];       // f2[b][c][t]          (atomically accumulated)
__device__ float g_f2cT[BB*TT*CC];       // f2c transposed [b][t][c]   (atomically accumulated)
__device__ float g_g   [BB*TT*CC];       // g[b][t][c] = f1c @ w       (atomically accumulated)
__device__ float g_s   [BB*TT*TT];       // sigmoid attention matrix

// ---------------- packed f32x2 helpers ----------------
__device__ __forceinline__ ull fma2(ull a, ull b, ull c){
    ull d;
    asm("fma.rn.f32x2 %0, %1, %2, %3;" : "=l"(d) : "l"(a), "l"(b), "l"(c));
    return d;
}
__device__ __forceinline__ ull add2(ull a, ull b){
    ull d;
    asm("add.rn.f32x2 %0, %1, %2;" : "=l"(d) : "l"(a), "l"(b));
    return d;
}
__device__ __forceinline__ ull pack2(float f){
    ull r;
    asm("mov.b64 %0, {%1, %1};" : "=l"(r) : "f"(f));
    return r;
}
__device__ __forceinline__ float2 unpk2(ull v){
    float2 f;
    asm("mov.b64 {%0, %1}, %2;" : "=f"(f.x), "=f"(f.y) : "l"(v));
    return f;
}

// ---------------- K0 (split in three so k1 lands on the ncu capture index) ----
__global__ void k0a_zero(){
    int idx = blockIdx.x * 256 + threadIdx.x;
    if (idx < BB*TT*NNODES) g_f1[idx] = 0.0f;
}
__global__ void k0b_zero(){
    int idx = blockIdx.x * 256 + threadIdx.x;
    if (idx < BB*CC*TT) g_f2[idx] = 0.0f;
}
__global__ void k0c_zero(){
    int idx = blockIdx.x * 256 + threadIdx.x;
    if (idx < BB*CC*TT){
        g_f2cT[idx] = 0.0f;
        g_g   [idx] = 0.0f;
    }
}

// ---------------- K1: fused dual weighted reduction over seq ----------------
// grid = 8b x 4ct x 32ns = 1024 blocks, block = 192, 2 blocks/SM.
// cp.async double-buffered chunks of (128c x 4n x 24t); XOR-swizzled smem tile
// (16B units, u ^ (c&7)); one LDS.128 feeds both reductions.
__device__ __forceinline__ void k1_stage(const float* gbase, float* buf, int ju, int c0s){
#pragma unroll
    for (int k2 = 0; k2 < 16; ++k2){
        const int c = c0s + 8*k2;
        const float* g = gbase + (size_t)c * (NNODES*TT);
        unsigned sa = (unsigned)__cvta_generic_to_shared(
            &buf[c*K1_PITCH + ((ju ^ (c & 7)) << 2)]);
        asm volatile("cp.async.cg.shared.global [%0], [%1], 16;" :: "r"(sa), "l"(g) : "memory");
    }
    asm volatile("cp.async.commit_group;" ::: "memory");
}

__global__ void __launch_bounds__(192, 2)
k1_reduce(const float* __restrict__ seq, const float* __restrict__ w1, const float* __restrict__ w2){
    extern __shared__ float sm[];
    float* buf0 = sm;
    float* buf1 = sm + K1_TILE;
    float* sw2n = sm + 2*K1_TILE;      // [64]
    float* f1st = sw2n + 64;           // [4 nn][24 t]

    const int blk = blockIdx.x;
    const int b   = blk >> 7;          // 0..7
    const int ct  = (blk >> 5) & 3;    // c-tile 0..3
    const int ns  = blk & 31;          // n-sweep 0..31 (64 n each)
    const int nb  = ns * 64;
    const int tid = threadIdx.x;
    const int w   = tid >> 5;          // warp -> t-quad
    const int lane= tid & 31;
    const int ju  = tid % 24;          // float4 unit within c-row segment (0..23)
    const int c0s = tid / 24;          // 0..7

    if (tid < 64) sw2n[tid] = w2[nb + tid];

    const float* seqbase = seq + ((size_t)(b*CC + ct*128) * NNODES + nb) * TT + ju*4;

    ull w1p[4];
#pragma unroll
    for (int kk = 0; kk < 4; ++kk) w1p[kk] = pack2(w1[ct*128 + lane + 32*kk]);

    ull acc[4][2];
#pragma unroll
    for (int kk = 0; kk < 4; ++kk){ acc[kk][0] = 0ull; acc[kk][1] = 0ull; }

    const int xm = lane & 7;

    k1_stage(seqbase, buf0, ju, c0s);

    for (int ch = 0; ch < 16; ++ch){
        float* cur = (ch & 1) ? buf1 : buf0;
        if (ch < 15){
            k1_stage(seqbase + (size_t)(ch+1)*K1_NC*TT, (ch & 1) ? buf0 : buf1, ju, c0s);
            asm volatile("cp.async.wait_group 1;" ::: "memory");
        } else {
            asm volatile("cp.async.wait_group 0;" ::: "memory");
        }
        __syncthreads();   // sync(A): buffer ready; prior f1st reads complete

        // ---- fused compute: one LDS.128 feeds both reductions ----
#pragma unroll
        for (int nn = 0; nn < K1_NC; ++nn){
            const ull w2p = pack2(sw2n[ch*K1_NC + nn]);
            const int u = 6*nn + w;
            const int so = ((u ^ xm) << 2);
            ull p0 = 0ull, p1 = 0ull;
#pragma unroll
            for (int kk = 0; kk < 4; ++kk){
                const ulonglong2 x = *reinterpret_cast<const ulonglong2*>(
                    &cur[(lane + 32*kk)*K1_PITCH + so]);
                acc[kk][0] = fma2(w2p, x.x, acc[kk][0]);
                acc[kk][1] = fma2(w2p, x.y, acc[kk][1]);
                p0 = fma2(w1p[kk], x.x, p0);
                p1 = fma2(w1p[kk], x.y, p1);
            }
#pragma unroll
            for (int off = 16; off > 0; off >>= 1){
                p0 = add2(p0, __shfl_xor_sync(0xffffffffu, p0, off));
                p1 = add2(p1, __shfl_xor_sync(0xffffffffu, p1, off));
            }
            if (lane == 0){
                float2 a = unpk2(p0), d = unpk2(p1);
                *reinterpret_cast<float4*>(&f1st[nn*24 + w*4]) = make_float4(a.x, a.y, d.x, d.y);
            }
        }
        __syncthreads();   // sync(B): f1st complete, tile reads done

        // ---- flush f1 partial (96 floats, coalesced in n) ----
        if (tid < 96){
            const int nn = tid / 24, t = tid - nn*24;
            atomicAdd(&g_f1[((size_t)b*TT + t)*NNODES + nb + ch*K1_NC + nn], f1st[nn*24 + t]);
        }
        // next iteration's sync(A) orders these reads before f1st is rewritten
    }

    // ---- flush f2 (register-resident across the 64-n sweep) ----
#pragma unroll
    for (int kk = 0; kk < 4; ++kk){
        const int c = ct*128 + lane + 32*kk;
        float* o = g_f2 + ((size_t)b*CC + c)*TT + w*4;
        float2 a = unpk2(acc[kk][0]), d = unpk2(acc[kk][1]);
        atomicAdd(o + 0, a.x);
        atomicAdd(o + 1, a.y);
        atomicAdd(o + 2, d.x);
        atomicAdd(o + 3, d.y);
    }
}

// ---------------- K2a: dilated conv of f1 over the n axis ----------------
__global__ void k2a_conv1(const float* __restrict__ Wd1){
    const int b  = blockIdx.x >> 4;
    const int n0 = (blockIdx.x & 15) * 128;
    __shared__ float s1[TT][130];
    __shared__ float sw[TT][48];
    for (int idx = threadIdx.x; idx < TT*48; idx += 256)
        ((float*)sw)[idx] = Wd1[idx];
    for (int idx = threadIdx.x; idx < TT*130; idx += 256){
        int i = idx / 130, jj = idx % 130;
        int n = n0 + jj - 1;
        s1[i][jj] = (n >= 0 && n < NNODES) ? g_f1[((size_t)b*TT + i)*NNODES + n] : 0.0f;
    }
    __syncthreads();
#pragma unroll
    for (int u = 0; u < 12; ++u){
        int idx = threadIdx.x + u*256;
        int t = idx >> 7, nl = idx & 127;
        float acc = 0.0f;
#pragma unroll
        for (int i = 0; i < TT; ++i)
            acc += s1[i][nl] * sw[t][2*i] + s1[i][nl+2] * sw[t][2*i+1];
        g_f1c[((size_t)b*TT + t)*NNODES + n0 + nl] = acc;
    }
}

// ---------------- K2b: dilated conv of f2 over the t axis (K-split GEMM) ----------------
__global__ void __launch_bounds__(256) k2b_conv2(const float* __restrict__ Wd2){
    const int o0 = (blockIdx.x & 15) * 32;
    const int i0 = (blockIdx.x >> 4) * 32;
    const int tid   = threadIdx.x;
    const int olane = tid & 31;
    const int b     = tid >> 5;

    __shared__ __align__(16) float  sf[32][8][26];
    __shared__ float2 sw2[32][33];

    {
        int i = tid >> 3, bb = tid & 7;
        sf[i][bb][0] = 0.0f; sf[i][bb][25] = 0.0f;
    }
#pragma unroll
    for (int u = 0; u < 24; ++u){
        int idx = tid + u*256;
        int i = idx / 192, r = idx % 192;
        int bb = r / 24, t = r % 24;
        sf[i][bb][t+1] = g_f2[((size_t)bb*CC + i0 + i)*TT + t];
    }
    const float2* wsrc = reinterpret_cast<const float2*>(Wd2);
#pragma unroll
    for (int u = 0; u < 4; ++u){
        int idx = tid + u*256;
        int oo = idx >> 5, iz = idx & 31;
        sw2[oo][iz] = wsrc[(size_t)(o0+oo)*CC + i0 + iz];
    }
    __syncthreads();

    ull acc[12];
#pragma unroll
    for (int u = 0; u < 12; ++u) acc[u] = 0ull;
#pragma unroll 4
    for (int iz = 0; iz < 32; ++iz){
        float2 wv = sw2[olane][iz];
        ull wx = pack2(wv.x), wy = pack2(wv.y);
        const ull* R = reinterpret_cast<const ull*>(&sf[iz][b][0]);
#pragma unroll
        for (int u = 0; u < 12; ++u){
            acc[u] = fma2(wx, R[u], acc[u]);
            acc[u] = fma2(wy, R[u+1], acc[u]);
        }
    }
    float* ob = g_f2cT + (size_t)b*TT*CC + o0 + olane;
#pragma unroll
    for (int u = 0; u < 12; ++u){
        float2 r = unpk2(acc[u]);
        atomicAdd(&ob[(2*u  )*CC], r.x);
        atomicAdd(&ob[(2*u+1)*CC], r.y);
    }
}

// ---------------- K2c: g[b,t,c] += sum_n f1c[b,t,n] * w[n,c]  (K-split x4) ----------------
__global__ void __launch_bounds__(192) k2c_gemm(const float* __restrict__ w){
    const int b  = blockIdx.x >> 6;
    const int c0 = ((blockIdx.x >> 2) & 15) * 32;
    const int ks = blockIdx.x & 3;
    const int tid = threadIdx.x;
    const int tq = tid >> 3;
    const int cq = tid & 7;
    __shared__ __align__(16) float sA[TT*129];
    __shared__ __align__(16) float sB[128*36];
    ull acc[2] = {0ull, 0ull};
    for (int kt = 0; kt < 4; ++kt){
        const int n0 = ks*512 + kt*128;
        for (int idx = tid; idx < 3072; idx += 192){
            int r = idx >> 7, col = idx & 127;
            sA[r*129 + col] = g_f1c[((size_t)b*TT + r)*NNODES + n0 + col];
        }
        for (int idx = tid; idx < 4096; idx += 192){
            int r = idx >> 5, cl = idx & 31;
            sB[r*36 + cl] = w[(size_t)(n0 + r)*CC + c0 + cl];
        }
        __syncthreads();
#pragma unroll 8
        for (int r = 0; r < 128; ++r){
            ull a0 = pack2(sA[tq*129 + r]);
            ulonglong2 bv = *reinterpret_cast<const ulonglong2*>(&sB[r*36 + cq*4]);
            acc[0] = fma2(a0, bv.x, acc[0]);
            acc[1] = fma2(a0, bv.y, acc[1]);
        }
        __syncthreads();
    }
    float2 r0 = unpk2(acc[0]), r1 = unpk2(acc[1]);
    float* o0 = g_g + ((size_t)b*TT + tq)*CC + c0 + cq*4;
    atomicAdd(&o0[0], r0.x);
    atomicAdd(&o0[1], r0.y);
    atomicAdd(&o0[2], r1.x);
    atomicAdd(&o0[3], r1.y);
}

// ---------------- K2d1: s[b,j,k] = sigmoid(g[b,j,:] . f2cT[b,k,:] + bias) ----------------
__global__ void __launch_bounds__(128) k2d1_attn(const float* __restrict__ bbias){
    const int b = blockIdx.x / 24;
    const int jj = blockIdx.x % 24;
    const int tid  = threadIdx.x;
    const int wrp  = tid >> 5;
    const int lane = tid & 31;
    __shared__ __align__(16) float sg[CC];
    const float* grow = g_g + ((size_t)b*TT + jj)*CC;
#pragma unroll
    for (int u = 0; u < 4; ++u) sg[tid + u*128] = grow[tid + u*128];
    __syncthreads();
    const ull* sg2 = reinterpret_cast<const ull*>(sg);
    const ull* f0  = reinterpret_cast<const ull*>(g_f2cT + ((size_t)b*TT + wrp*6)*CC);
    ull acc[6] = {0ull,0ull,0ull,0ull,0ull,0ull};
#pragma unroll
    for (int it = 0; it < 8; ++it){
        ull gv = sg2[lane + it*32];
#pragma unroll
        for (int kk = 0; kk < 6; ++kk)
            acc[kk] = fma2(f0[(size_t)kk*256 + lane + it*32], gv, acc[kk]);
    }
#pragma unroll
    for (int kk = 0; kk < 6; ++kk)
#pragma unroll
        for (int off = 16; off > 0; off >>= 1)
            acc[kk] = add2(acc[kk], __shfl_xor_sync(0xffffffffu, acc[kk], off));
    if (lane < 6){
        int k = wrp*6 + lane;
        float2 aa = unpk2(acc[lane]);
        float sv = aa.x + aa.y + bbias[jj*TT + k];
        g_s[((size_t)b*TT + jj)*TT + k] = 1.0f/(1.0f + __expf(-sv));
    }
}

// ---------------- K2d2: l = v @ s; BN + mask + softmax (single block) ----------------
__global__ void k2d2_final(const float* __restrict__ v, const float* __restrict__ gamma,
                           const float* __restrict__ beta, float* __restrict__ out){
    const int tid = threadIdx.x;
    __shared__ float ss[BB][TT][TT];
    __shared__ float sv[TT][TT];
    __shared__ float sl[192][25];
    __shared__ float smean[TT], sinv[TT];
    for (int idx = tid; idx < BB*TT*TT; idx += 192) ((float*)ss)[idx] = g_s[idx];
    for (int idx = tid; idx < TT*TT;   idx += 192) ((float*)sv)[idx] = v[idx];
    __syncthreads();
    const int b = tid / TT, i = tid % TT;
    float l[TT];
#pragma unroll
    for (int k = 0; k < TT; ++k) l[k] = 0.0f;
#pragma unroll
    for (int jj = 0; jj < TT; ++jj){
        float vij = sv[i][jj];
#pragma unroll
        for (int k = 0; k < TT; ++k) l[k] = fmaf(vij, ss[b][jj][k], l[k]);
    }
#pragma unroll
    for (int k = 0; k < TT; ++k) sl[tid][k] = l[k];
    __syncthreads();
    if (tid < TT){
        float s = 0.0f, s2 = 0.0f;
        for (int r = 0; r < 192; ++r){ float x = sl[r][tid]; s += x; s2 = fmaf(x, x, s2); }
        float m = s * (1.0f/192.0f);
        smean[tid] = m;
        sinv[tid]  = rsqrtf(s2 * (1.0f/192.0f) - m*m + 1e-5f);
    }
    __syncthreads();
    float mx = -3.4e38f;
#pragma unroll
    for (int k = 0; k < TT; ++k){
        float y = (l[k] - smean[k]) * sinv[k] * gamma[k] + beta[k];
        if ((i < 12) != (k < 12)) y -= 1e13f;
        l[k] = y;
        mx = fmaxf(mx, y);
    }
    float s = 0.0f;
#pragma unroll
    for (int k = 0; k < TT; ++k){ float e = __expf(l[k] - mx); l[k] = e; s += e; }
    float inv = 1.0f / s;
#pragma unroll
    for (int k = 0; k < TT; ++k)
        out[((size_t)b*TT + i)*TT + k] = l[k] * inv;
}

// ---------------- launch ----------------
extern "C" void kernel_launch(void* const* d_in, const int* in_sizes, int n_in,
                              void* d_out, int out_size){
    const float* seq   = (const float*)d_in[0];
    const float* w1    = (const float*)d_in[1];
    const float* w2    = (const float*)d_in[2];
    const float* Wd1   = (const float*)d_in[3];
    const float* Wd2   = (const float*)d_in[4];
    const float* w     = (const float*)d_in[5];
    const float* bbias = (const float*)d_in[6];
    const float* v     = (const float*)d_in[7];
    const float* gamma = (const float*)d_in[8];
    const float* beta  = (const float*)d_in[9];
    float* out = (float*)d_out;

    cudaFuncSetAttribute(k1_reduce, cudaFuncAttributeMaxDynamicSharedMemorySize, K1_SMEM);

    // three zero kernels shift k1 to raw launch index 5 == the ncu capture slot
    k0a_zero  <<<(BB*TT*NNODES + 255)/256, 256>>>();
    k0b_zero  <<<(BB*CC*TT + 255)/256, 256>>>();
    k0c_zero  <<<(BB*CC*TT + 255)/256, 256>>>();
    k1_reduce <<<1024, 192, K1_SMEM>>>(seq, w1, w2);
    k2a_conv1 <<<BB*16, 256>>>(Wd1);
    k2b_conv2 <<<256, 256>>>(Wd2);
    k2c_gemm  <<<512, 192>>>(w);
    k2d1_attn <<<BB*TT, 128>>>(bbias);
    k2d2_final<<<1, 192>>>(v, gamma, beta, out);
}

// round 13
// speedup vs baseline: 1.1414x; 1.1311x over previous
#include <cuda_runtime.h>
#include <cstdint>

#define BB 8
#define CC 512
#define NNODES 2048
#define TT 24

#define K1_NC    4                          // n per chunk
#define K1_PITCH 96                         // words per c-row segment (4n*24t)
#define K1_TILE  (128*K1_PITCH)             // words per buffer (48 KB)
#define K1_SMEM  ((2*K1_TILE + 160) * 4)    // two buffers + w2 slice + f1 stage

// k2b dynamic smem layout (floats): sf[512*26] | swx[32*65] | swy[32*65] | part(ull)[8*12*32]
#define K2B_SF    (512*26)
#define K2B_SWX   (K2B_SF)
#define K2B_SWY   (K2B_SWX + 32*65)
#define K2B_PART  (K2B_SWY + 32*65)          // 17472 words -> 8B aligned
#define K2B_SMEM  ((K2B_PART + 8*12*32*2) * 4)

typedef unsigned long long ull;

// ---------------- scratch (static device arrays; no allocation) ----------------
__device__ float g_f1  [BB*TT*NNODES];   // f1[b][t][n]          (atomically accumulated)
__device__ float g_f2  [BB*CC*TT];       // f2[b][c][t]          (atomically accumulated)
__device__ float g_f2cT[BB*TT*CC];       // f2c transposed [b][t][c]   (plain stores)
__device__ float g_g   [BB*TT*CC];       // g[b][t][c] = f1c @ w       (red.v4 accumulated)
__device__ float g_s   [BB*TT*TT];       // sigmoid attention matrix

// ---------------- packed f32x2 helpers ----------------
__device__ __forceinline__ ull fma2(ull a, ull b, ull c){
    ull d;
    asm("fma.rn.f32x2 %0, %1, %2, %3;" : "=l"(d) : "l"(a), "l"(b), "l"(c));
    return d;
}
__device__ __forceinline__ ull add2(ull a, ull b){
    ull d;
    asm("add.rn.f32x2 %0, %1, %2;" : "=l"(d) : "l"(a), "l"(b));
    return d;
}
__device__ __forceinline__ ull pack2(float f){
    ull r;
    asm("mov.b64 %0, {%1, %1};" : "=l"(r) : "f"(f));
    return r;
}
__device__ __forceinline__ float2 unpk2(ull v){
    float2 f;
    asm("mov.b64 {%0, %1}, %2;" : "=f"(f.x), "=f"(f.y) : "l"(v));
    return f;
}

// ---------------- K0: zero all accumulated scratch (one kernel) ----------------
__global__ void k0_zero(){
    int idx = blockIdx.x * 256 + threadIdx.x;
    if (idx < BB*TT*NNODES) g_f1[idx] = 0.0f;
    if (idx < BB*CC*TT){
        g_f2[idx] = 0.0f;
        g_g [idx] = 0.0f;
    }
}

// ---------------- K1: fused dual weighted reduction over seq (unchanged) ----------------
__device__ __forceinline__ void k1_stage(const float* gbase, float* buf, int ju, int c0s){
#pragma unroll
    for (int k2 = 0; k2 < 16; ++k2){
        const int c = c0s + 8*k2;
        const float* g = gbase + (size_t)c * (NNODES*TT);
        unsigned sa = (unsigned)__cvta_generic_to_shared(
            &buf[c*K1_PITCH + ((ju ^ (c & 7)) << 2)]);
        asm volatile("cp.async.cg.shared.global [%0], [%1], 16;" :: "r"(sa), "l"(g) : "memory");
    }
    asm volatile("cp.async.commit_group;" ::: "memory");
}

__global__ void __launch_bounds__(192, 2)
k1_reduce(const float* __restrict__ seq, const float* __restrict__ w1, const float* __restrict__ w2){
    extern __shared__ float sm[];
    float* buf0 = sm;
    float* buf1 = sm + K1_TILE;
    float* sw2n = sm + 2*K1_TILE;      // [64]
    float* f1st = sw2n + 64;           // [4 nn][24 t]

    const int blk = blockIdx.x;
    const int b   = blk >> 7;
    const int ct  = (blk >> 5) & 3;
    const int ns  = blk & 31;
    const int nb  = ns * 64;
    const int tid = threadIdx.x;
    const int w   = tid >> 5;
    const int lane= tid & 31;
    const int ju  = tid % 24;
    const int c0s = tid / 24;

    if (tid < 64) sw2n[tid] = w2[nb + tid];

    const float* seqbase = seq + ((size_t)(b*CC + ct*128) * NNODES + nb) * TT + ju*4;

    ull w1p[4];
#pragma unroll
    for (int kk = 0; kk < 4; ++kk) w1p[kk] = pack2(w1[ct*128 + lane + 32*kk]);

    ull acc[4][2];
#pragma unroll
    for (int kk = 0; kk < 4; ++kk){ acc[kk][0] = 0ull; acc[kk][1] = 0ull; }

    const int xm = lane & 7;

    k1_stage(seqbase, buf0, ju, c0s);

    for (int ch = 0; ch < 16; ++ch){
        float* cur = (ch & 1) ? buf1 : buf0;
        if (ch < 15){
            k1_stage(seqbase + (size_t)(ch+1)*K1_NC*TT, (ch & 1) ? buf0 : buf1, ju, c0s);
            asm volatile("cp.async.wait_group 1;" ::: "memory");
        } else {
            asm volatile("cp.async.wait_group 0;" ::: "memory");
        }
        __syncthreads();

#pragma unroll
        for (int nn = 0; nn < K1_NC; ++nn){
            const ull w2p = pack2(sw2n[ch*K1_NC + nn]);
            const int u = 6*nn + w;
            const int so = ((u ^ xm) << 2);
            ull p0 = 0ull, p1 = 0ull;
#pragma unroll
            for (int kk = 0; kk < 4; ++kk){
                const ulonglong2 x = *reinterpret_cast<const ulonglong2*>(
                    &cur[(lane + 32*kk)*K1_PITCH + so]);
                acc[kk][0] = fma2(w2p, x.x, acc[kk][0]);
                acc[kk][1] = fma2(w2p, x.y, acc[kk][1]);
                p0 = fma2(w1p[kk], x.x, p0);
                p1 = fma2(w1p[kk], x.y, p1);
            }
#pragma unroll
            for (int off = 16; off > 0; off >>= 1){
                p0 = add2(p0, __shfl_xor_sync(0xffffffffu, p0, off));
                p1 = add2(p1, __shfl_xor_sync(0xffffffffu, p1, off));
            }
            if (lane == 0){
                float2 a = unpk2(p0), d = unpk2(p1);
                *reinterpret_cast<float4*>(&f1st[nn*24 + w*4]) = make_float4(a.x, a.y, d.x, d.y);
            }
        }
        __syncthreads();

        if (tid < 96){
            const int nn = tid / 24, t = tid - nn*24;
            atomicAdd(&g_f1[((size_t)b*TT + t)*NNODES + nb + ch*K1_NC + nn], f1st[nn*24 + t]);
        }
    }

#pragma unroll
    for (int kk = 0; kk < 4; ++kk){
        const int c = ct*128 + lane + 32*kk;
        float* o = g_f2 + ((size_t)b*CC + c)*TT + w*4;
        float2 a = unpk2(acc[kk][0]), d = unpk2(acc[kk][1]);
        atomicAdd(o + 0, a.x);
        atomicAdd(o + 1, a.y);
        atomicAdd(o + 2, d.x);
        atomicAdd(o + 3, d.y);
    }
}

// ---------------- K2b: dilated conv of f2 over t, ATOMIC-FREE ----------------
// f2cT[b,t,o] = sum_i Wd2[o,i,0]*f2[b,i,t-1] + Wd2[o,i,1]*f2[b,i,t+1]
// grid = 8b x 16 o-chunks = 128 blocks, block = 256 (32 olane x 8 ig-warps).
// Full i=512 per block; warp partials reduced through smem; plain STG.
__global__ void __launch_bounds__(256) k2b_conv2(const float* __restrict__ Wd2){
    extern __shared__ float smb[];
    float* sf  = smb;                    // [512][26], j = t+1, halo at 0/25
    float* swx = smb + K2B_SWX;          // [32][65]
    float* swy = smb + K2B_SWY;          // [32][65]
    ull*   part= reinterpret_cast<ull*>(smb + K2B_PART);  // [8][12][32]

    const int b  = blockIdx.x >> 4;
    const int o0 = (blockIdx.x & 15) * 32;
    const int tid   = threadIdx.x;
    const int olane = tid & 31;
    const int ig    = tid >> 5;          // warp id

    // halo zeros
    for (int i = tid; i < 512; i += 256){ sf[i*26] = 0.0f; sf[i*26 + 25] = 0.0f; }
    // stage full f2 slice (contiguous in global)
    const float* f2b = g_f2 + (size_t)b*CC*TT;
#pragma unroll
    for (int u = 0; u < 48; ++u){
        int idx = tid + u*256;           // 0..12287
        int i = idx / 24, t = idx - i*24;
        sf[i*26 + t + 1] = f2b[idx];
    }

    ull acc[12];
#pragma unroll
    for (int u = 0; u < 12; ++u) acc[u] = 0ull;

    const float2* wsrc = reinterpret_cast<const float2*>(Wd2);
    for (int r = 0; r < 8; ++r){
        __syncthreads();   // sf ready (r=0); prior round's swx reads done (r>0)
#pragma unroll
        for (int u = 0; u < 8; ++u){
            int idx = tid + u*256;       // 0..2047
            int oo = idx >> 6, iz = idx & 63;
            float2 wv = wsrc[(size_t)(o0+oo)*CC + r*64 + iz];
            swx[oo*65 + iz] = wv.x;
            swy[oo*65 + iz] = wv.y;
        }
        __syncthreads();
#pragma unroll
        for (int q = 0; q < 8; ++q){
            const int li = ig*8 + q;
            const int i  = r*64 + li;
            ull wx = pack2(swx[olane*65 + li]);
            ull wy = pack2(swy[olane*65 + li]);
            const ull* R = reinterpret_cast<const ull*>(&sf[i*26]);  // broadcast
#pragma unroll
            for (int u = 0; u < 12; ++u){
                acc[u] = fma2(wx, R[u], acc[u]);
                acc[u] = fma2(wy, R[u+1], acc[u]);
            }
        }
    }
    __syncthreads();
#pragma unroll
    for (int u = 0; u < 12; ++u) part[(ig*12 + u)*32 + olane] = acc[u];
    __syncthreads();
    // reduce 8 warp-partials, store: o = tid&31, t = 3*(tid>>5)+q
    const int oo = tid & 31;
    const int tb = (tid >> 5) * 3;
#pragma unroll
    for (int q = 0; q < 3; ++q){
        const int t = tb + q;
        const int ttp = t >> 1, half = t & 1;
        float s = 0.0f;
#pragma unroll
        for (int g2 = 0; g2 < 8; ++g2){
            float2 p = unpk2(part[(g2*12 + ttp)*32 + oo]);
            s += half ? p.y : p.x;
        }
        g_f2cT[(size_t)b*TT*CC + (size_t)t*CC + o0 + oo] = s;
    }
}

// ---------------- K2ac: FUSED dilated-conv(f1) + GEMM into g ----------------
// phase1: f1c[t][nl] tile (24 x 64) in smem (splatted ull)
// phase2: g[b,t,c] += sum_nl f1c[t][nl] * w[n0+nl][c], red.v4 flush
// grid = 8b x 32 n-chunks = 256 blocks, block = 256 (2 t-halves x 128 c-quads)
__global__ void __launch_bounds__(256) k2ac_fused(const float* __restrict__ Wd1,
                                                  const float* __restrict__ w){
    const int b  = blockIdx.x >> 5;
    const int n0 = (blockIdx.x & 31) * 64;
    const int tid = threadIdx.x;

    __shared__ float s1[TT][66];     // j <-> n = n0 + j - 1
    __shared__ float sw[TT][48];
    __shared__ ull  sf2[TT][64];     // splatted f1c tile

    for (int idx = tid; idx < TT*48; idx += 256) ((float*)sw)[idx] = Wd1[idx];
    for (int idx = tid; idx < TT*66; idx += 256){
        int i = idx / 66, j = idx - i*66;
        int n = n0 + j - 1;
        s1[i][j] = (n >= 0 && n < NNODES) ? g_f1[((size_t)b*TT + i)*NNODES + n] : 0.0f;
    }
    __syncthreads();
#pragma unroll
    for (int u = 0; u < 6; ++u){
        int idx = tid + u*256;           // 0..1535
        int t = idx >> 6, nl = idx & 63;
        float acc = 0.0f;
#pragma unroll
        for (int i = 0; i < TT; ++i)
            acc += s1[i][nl] * sw[t][2*i] + s1[i][nl+2] * sw[t][2*i+1];
        sf2[t][nl] = pack2(acc);
    }
    __syncthreads();

    const int th = tid >> 7;             // t-half 0..1
    const int cq = tid & 127;            // c-quad
    ull acc[12][2];
#pragma unroll
    for (int tt = 0; tt < 12; ++tt){ acc[tt][0] = 0ull; acc[tt][1] = 0ull; }

    const float* wbase = w + (size_t)n0*CC + 4*cq;
#pragma unroll 4
    for (int nl = 0; nl < 64; ++nl){
        const ulonglong2 wp = *reinterpret_cast<const ulonglong2*>(wbase + (size_t)nl*CC);
#pragma unroll
        for (int tt = 0; tt < 12; ++tt){
            ull fv = sf2[th*12 + tt][nl];    // LDS.64 broadcast
            acc[tt][0] = fma2(fv, wp.x, acc[tt][0]);
            acc[tt][1] = fma2(fv, wp.y, acc[tt][1]);
        }
    }
#pragma unroll
    for (int tt = 0; tt < 12; ++tt){
        float2 a = unpk2(acc[tt][0]), d = unpk2(acc[tt][1]);
        float* gp = &g_g[((size_t)b*TT + th*12 + tt)*CC + 4*cq];
        asm volatile("red.global.add.v4.f32 [%0], {%1,%2,%3,%4};"
                     :: "l"(gp), "f"(a.x), "f"(a.y), "f"(d.x), "f"(d.y) : "memory");
    }
}

// ---------------- K2d1: s[b,j,k] = sigmoid(g[b,j,:] . f2cT[b,k,:] + bias) ----------------
__global__ void __launch_bounds__(128) k2d1_attn(const float* __restrict__ bbias){
    const int b = blockIdx.x / 24;
    const int jj = blockIdx.x % 24;
    const int tid  = threadIdx.x;
    const int wrp  = tid >> 5;
    const int lane = tid & 31;
    __shared__ __align__(16) float sg[CC];
    const float* grow = g_g + ((size_t)b*TT + jj)*CC;
#pragma unroll
    for (int u = 0; u < 4; ++u) sg[tid + u*128] = grow[tid + u*128];
    __syncthreads();
    const ull* sg2 = reinterpret_cast<const ull*>(sg);
    const ull* f0  = reinterpret_cast<const ull*>(g_f2cT + ((size_t)b*TT + wrp*6)*CC);
    ull acc[6] = {0ull,0ull,0ull,0ull,0ull,0ull};
#pragma unroll
    for (int it = 0; it < 8; ++it){
        ull gv = sg2[lane + it*32];
#pragma unroll
        for (int kk = 0; kk < 6; ++kk)
            acc[kk] = fma2(f0[(size_t)kk*256 + lane + it*32], gv, acc[kk]);
    }
#pragma unroll
    for (int kk = 0; kk < 6; ++kk)
#pragma unroll
        for (int off = 16; off > 0; off >>= 1)
            acc[kk] = add2(acc[kk], __shfl_xor_sync(0xffffffffu, acc[kk], off));
    if (lane < 6){
        int k = wrp*6 + lane;
        float2 aa = unpk2(acc[lane]);
        float sv = aa.x + aa.y + bbias[jj*TT + k];
        g_s[((size_t)b*TT + jj)*TT + k] = 1.0f/(1.0f + __expf(-sv));
    }
}

// ---------------- K2d2: l = v @ s; BN + mask + softmax (single block) ----------------
__global__ void k2d2_final(const float* __restrict__ v, const float* __restrict__ gamma,
                           const float* __restrict__ beta, float* __restrict__ out){
    const int tid = threadIdx.x;
    __shared__ float ss[BB][TT][TT];
    __shared__ float sv[TT][TT];
    __shared__ float sl[192][25];
    __shared__ float smean[TT], sinv[TT];
    for (int idx = tid; idx < BB*TT*TT; idx += 192) ((float*)ss)[idx] = g_s[idx];
    for (int idx = tid; idx < TT*TT;   idx += 192) ((float*)sv)[idx] = v[idx];
    __syncthreads();
    const int b = tid / TT, i = tid % TT;
    float l[TT];
#pragma unroll
    for (int k = 0; k < TT; ++k) l[k] = 0.0f;
#pragma unroll
    for (int jj = 0; jj < TT; ++jj){
        float vij = sv[i][jj];
#pragma unroll
        for (int k = 0; k < TT; ++k) l[k] = fmaf(vij, ss[b][jj][k], l[k]);
    }
#pragma unroll
    for (int k = 0; k < TT; ++k) sl[tid][k] = l[k];
    __syncthreads();
    if (tid < TT){
        float s = 0.0f, s2 = 0.0f;
        for (int r = 0; r < 192; ++r){ float x = sl[r][tid]; s += x; s2 = fmaf(x, x, s2); }
        float m = s * (1.0f/192.0f);
        smean[tid] = m;
        sinv[tid]  = rsqrtf(s2 * (1.0f/192.0f) - m*m + 1e-5f);
    }
    __syncthreads();
    float mx = -3.4e38f;
#pragma unroll
    for (int k = 0; k < TT; ++k){
        float y = (l[k] - smean[k]) * sinv[k] * gamma[k] + beta[k];
        if ((i < 12) != (k < 12)) y -= 1e13f;
        l[k] = y;
        mx = fmaxf(mx, y);
    }
    float s = 0.0f;
#pragma unroll
    for (int k = 0; k < TT; ++k){ float e = __expf(l[k] - mx); l[k] = e; s += e; }
    float inv = 1.0f / s;
#pragma unroll
    for (int k = 0; k < TT; ++k)
        out[((size_t)b*TT + i)*TT + k] = l[k] * inv;
}

// ---------------- launch ----------------
extern "C" void kernel_launch(void* const* d_in, const int* in_sizes, int n_in,
                              void* d_out, int out_size){
    const float* seq   = (const float*)d_in[0];
    const float* w1    = (const float*)d_in[1];
    const float* w2    = (const float*)d_in[2];
    const float* Wd1   = (const float*)d_in[3];
    const float* Wd2   = (const float*)d_in[4];
    const float* w     = (const float*)d_in[5];
    const float* bbias = (const float*)d_in[6];
    const float* v     = (const float*)d_in[7];
    const float* gamma = (const float*)d_in[8];
    const float* beta  = (const float*)d_in[9];
    float* out = (float*)d_out;

    cudaFuncSetAttribute(k1_reduce, cudaFuncAttributeMaxDynamicSharedMemorySize, K1_SMEM);
    cudaFuncSetAttribute(k2b_conv2, cudaFuncAttributeMaxDynamicSharedMemorySize, K2B_SMEM);

    // order: 4th launch (k2ac_fused) is the ncu capture slot
    k0_zero   <<<(BB*TT*NNODES + 255)/256, 256>>>();
    k1_reduce <<<1024, 192, K1_SMEM>>>(seq, w1, w2);
    k2b_conv2 <<<128, 256, K2B_SMEM>>>(Wd2);
    k2ac_fused<<<256, 256>>>(Wd1, w);
    k2d1_attn <<<BB*TT, 128>>>(bbias);
    k2d2_final<<<1, 192>>>(v, gamma, beta, out);
}

// round 14
// speedup vs baseline: 1.1808x; 1.0345x over previous
#include <cuda_runtime.h>
#include <cstdint>

#define BB 8
#define CC 512
#define NNODES 2048
#define TT 24

#define K1_NC    4                          // n per chunk
#define K1_PITCH 96                         // words per c-row segment (4n*24t)
#define K1_TILE  (128*K1_PITCH)             // words per buffer (48 KB)
#define K1_SMEM  ((2*K1_TILE + 160) * 4)    // two buffers + w2 slice + f1 stage

// k2b dynamic smem layout (floats): sf[512*26] | swx[32*65] | swy[32*65] | part(ull)[8*12*32]
#define K2B_SF    (512*26)
#define K2B_SWX   (K2B_SF)
#define K2B_SWY   (K2B_SWX + 32*65)
#define K2B_PART  (K2B_SWY + 32*65)          // 17472 words -> 8B aligned
#define K2B_SMEM  ((K2B_PART + 8*12*32*2) * 4)

typedef unsigned long long ull;

// ---------------- scratch (static device arrays; no allocation) ----------------
__device__ float g_f1  [BB*TT*NNODES];   // f1[b][t][n]          (atomically accumulated)
__device__ float g_f2  [BB*CC*TT];       // f2[b][c][t]          (atomically accumulated)
__device__ float g_f2cT[BB*TT*CC];       // f2c transposed [b][t][c]   (plain stores)
__device__ float g_g   [BB*TT*CC];       // g[b][t][c] = f1c @ w       (red.v4 accumulated)
__device__ float g_s   [BB*TT*TT];       // sigmoid attention matrix

// ---------------- packed f32x2 helpers ----------------
__device__ __forceinline__ ull fma2(ull a, ull b, ull c){
    ull d;
    asm("fma.rn.f32x2 %0, %1, %2, %3;" : "=l"(d) : "l"(a), "l"(b), "l"(c));
    return d;
}
__device__ __forceinline__ ull add2(ull a, ull b){
    ull d;
    asm("add.rn.f32x2 %0, %1, %2;" : "=l"(d) : "l"(a), "l"(b));
    return d;
}
__device__ __forceinline__ ull pack2(float f){
    ull r;
    asm("mov.b64 %0, {%1, %1};" : "=l"(r) : "f"(f));
    return r;
}
__device__ __forceinline__ float2 unpk2(ull v){
    float2 f;
    asm("mov.b64 {%0, %1}, %2;" : "=f"(f.x), "=f"(f.y) : "l"(v));
    return f;
}

// ---------------- K0: zero all accumulated scratch (one kernel) ----------------
__global__ void k0_zero(){
    int idx = blockIdx.x * 256 + threadIdx.x;
    if (idx < BB*TT*NNODES) g_f1[idx] = 0.0f;
    if (idx < BB*CC*TT){
        g_f2[idx] = 0.0f;
        g_g [idx] = 0.0f;
    }
}

// ---------------- K1: fused dual weighted reduction over seq (unchanged) ----------------
__device__ __forceinline__ void k1_stage(const float* gbase, float* buf, int ju, int c0s){
#pragma unroll
    for (int k2 = 0; k2 < 16; ++k2){
        const int c = c0s + 8*k2;
        const float* g = gbase + (size_t)c * (NNODES*TT);
        unsigned sa = (unsigned)__cvta_generic_to_shared(
            &buf[c*K1_PITCH + ((ju ^ (c & 7)) << 2)]);
        asm volatile("cp.async.cg.shared.global [%0], [%1], 16;" :: "r"(sa), "l"(g) : "memory");
    }
    asm volatile("cp.async.commit_group;" ::: "memory");
}

__global__ void __launch_bounds__(192, 2)
k1_reduce(const float* __restrict__ seq, const float* __restrict__ w1, const float* __restrict__ w2){
    extern __shared__ float sm[];
    float* buf0 = sm;
    float* buf1 = sm + K1_TILE;
    float* sw2n = sm + 2*K1_TILE;      // [64]
    float* f1st = sw2n + 64;           // [4 nn][24 t]

    const int blk = blockIdx.x;
    const int b   = blk >> 7;
    const int ct  = (blk >> 5) & 3;
    const int ns  = blk & 31;
    const int nb  = ns * 64;
    const int tid = threadIdx.x;
    const int w   = tid >> 5;
    const int lane= tid & 31;
    const int ju  = tid % 24;
    const int c0s = tid / 24;

    if (tid < 64) sw2n[tid] = w2[nb + tid];

    const float* seqbase = seq + ((size_t)(b*CC + ct*128) * NNODES + nb) * TT + ju*4;

    ull w1p[4];
#pragma unroll
    for (int kk = 0; kk < 4; ++kk) w1p[kk] = pack2(w1[ct*128 + lane + 32*kk]);

    ull acc[4][2];
#pragma unroll
    for (int kk = 0; kk < 4; ++kk){ acc[kk][0] = 0ull; acc[kk][1] = 0ull; }

    const int xm = lane & 7;

    k1_stage(seqbase, buf0, ju, c0s);

    for (int ch = 0; ch < 16; ++ch){
        float* cur = (ch & 1) ? buf1 : buf0;
        if (ch < 15){
            k1_stage(seqbase + (size_t)(ch+1)*K1_NC*TT, (ch & 1) ? buf0 : buf1, ju, c0s);
            asm volatile("cp.async.wait_group 1;" ::: "memory");
        } else {
            asm volatile("cp.async.wait_group 0;" ::: "memory");
        }
        __syncthreads();

#pragma unroll
        for (int nn = 0; nn < K1_NC; ++nn){
            const ull w2p = pack2(sw2n[ch*K1_NC + nn]);
            const int u = 6*nn + w;
            const int so = ((u ^ xm) << 2);
            ull p0 = 0ull, p1 = 0ull;
#pragma unroll
            for (int kk = 0; kk < 4; ++kk){
                const ulonglong2 x = *reinterpret_cast<const ulonglong2*>(
                    &cur[(lane + 32*kk)*K1_PITCH + so]);
                acc[kk][0] = fma2(w2p, x.x, acc[kk][0]);
                acc[kk][1] = fma2(w2p, x.y, acc[kk][1]);
                p0 = fma2(w1p[kk], x.x, p0);
                p1 = fma2(w1p[kk], x.y, p1);
            }
#pragma unroll
            for (int off = 16; off > 0; off >>= 1){
                p0 = add2(p0, __shfl_xor_sync(0xffffffffu, p0, off));
                p1 = add2(p1, __shfl_xor_sync(0xffffffffu, p1, off));
            }
            if (lane == 0){
                float2 a = unpk2(p0), d = unpk2(p1);
                *reinterpret_cast<float4*>(&f1st[nn*24 + w*4]) = make_float4(a.x, a.y, d.x, d.y);
            }
        }
        __syncthreads();

        if (tid < 96){
            const int nn = tid / 24, t = tid - nn*24;
            atomicAdd(&g_f1[((size_t)b*TT + t)*NNODES + nb + ch*K1_NC + nn], f1st[nn*24 + t]);
        }
    }

#pragma unroll
    for (int kk = 0; kk < 4; ++kk){
        const int c = ct*128 + lane + 32*kk;
        float* o = g_f2 + ((size_t)b*CC + c)*TT + w*4;
        float2 a = unpk2(acc[kk][0]), d = unpk2(acc[kk][1]);
        atomicAdd(o + 0, a.x);
        atomicAdd(o + 1, a.y);
        atomicAdd(o + 2, d.x);
        atomicAdd(o + 3, d.y);
    }
}

// ---------------- K2b: dilated conv of f2 over t, ATOMIC-FREE (unchanged) ----------------
__global__ void __launch_bounds__(256) k2b_conv2(const float* __restrict__ Wd2){
    extern __shared__ float smb[];
    float* sf  = smb;                    // [512][26], j = t+1, halo at 0/25
    float* swx = smb + K2B_SWX;          // [32][65]
    float* swy = smb + K2B_SWY;          // [32][65]
    ull*   part= reinterpret_cast<ull*>(smb + K2B_PART);  // [8][12][32]

    const int b  = blockIdx.x >> 4;
    const int o0 = (blockIdx.x & 15) * 32;
    const int tid   = threadIdx.x;
    const int olane = tid & 31;
    const int ig    = tid >> 5;

    for (int i = tid; i < 512; i += 256){ sf[i*26] = 0.0f; sf[i*26 + 25] = 0.0f; }
    const float* f2b = g_f2 + (size_t)b*CC*TT;
#pragma unroll
    for (int u = 0; u < 48; ++u){
        int idx = tid + u*256;
        int i = idx / 24, t = idx - i*24;
        sf[i*26 + t + 1] = f2b[idx];
    }

    ull acc[12];
#pragma unroll
    for (int u = 0; u < 12; ++u) acc[u] = 0ull;

    const float2* wsrc = reinterpret_cast<const float2*>(Wd2);
    for (int r = 0; r < 8; ++r){
        __syncthreads();
#pragma unroll
        for (int u = 0; u < 8; ++u){
            int idx = tid + u*256;
            int oo = idx >> 6, iz = idx & 63;
            float2 wv = wsrc[(size_t)(o0+oo)*CC + r*64 + iz];
            swx[oo*65 + iz] = wv.x;
            swy[oo*65 + iz] = wv.y;
        }
        __syncthreads();
#pragma unroll
        for (int q = 0; q < 8; ++q){
            const int li = ig*8 + q;
            const int i  = r*64 + li;
            ull wx = pack2(swx[olane*65 + li]);
            ull wy = pack2(swy[olane*65 + li]);
            const ull* R = reinterpret_cast<const ull*>(&sf[i*26]);
#pragma unroll
            for (int u = 0; u < 12; ++u){
                acc[u] = fma2(wx, R[u], acc[u]);
                acc[u] = fma2(wy, R[u+1], acc[u]);
            }
        }
    }
    __syncthreads();
#pragma unroll
    for (int u = 0; u < 12; ++u) part[(ig*12 + u)*32 + olane] = acc[u];
    __syncthreads();
    const int oo = tid & 31;
    const int tb = (tid >> 5) * 3;
#pragma unroll
    for (int q = 0; q < 3; ++q){
        const int t = tb + q;
        const int ttp = t >> 1, half = t & 1;
        float s = 0.0f;
#pragma unroll
        for (int g2 = 0; g2 < 8; ++g2){
            float2 p = unpk2(part[(g2*12 + ttp)*32 + oo]);
            s += half ? p.y : p.x;
        }
        g_f2cT[(size_t)b*TT*CC + (size_t)t*CC + o0 + oo] = s;
    }
}

// ---------------- K2ac: FUSED dilated-conv(f1) + GEMM, cp.async-staged w ----------------
// phase1: f1c[t][nl] tile (24 x 64) in smem (splatted ull)
// phase2: w tiles (8 n x 512 c) double-buffered via cp.async; g += f1c @ w; red.v4
// grid = 8b x 32 n-chunks = 256 blocks, block = 256 (2 t-halves x 128 c-quads)
__global__ void __launch_bounds__(256, 2) k2ac_fused(const float* __restrict__ Wd1,
                                                     const float* __restrict__ w){
    __shared__ __align__(16) float pool[8192];   // phase1: s1|sw ; phase2: wbuf0|wbuf1
    __shared__ ull sf2[TT][64];                  // splatted f1c tile

    const int b  = blockIdx.x >> 5;
    const int n0 = (blockIdx.x & 31) * 64;
    const int tid = threadIdx.x;

    float* s1 = pool;                 // [24][66]
    float* sw = pool + TT*66;         // [24][48]

    for (int idx = tid; idx < TT*48; idx += 256) sw[idx] = Wd1[idx];
    for (int idx = tid; idx < TT*66; idx += 256){
        int i = idx / 66, j = idx - i*66;
        int n = n0 + j - 1;
        s1[i*66 + j] = (n >= 0 && n < NNODES) ? g_f1[((size_t)b*TT + i)*NNODES + n] : 0.0f;
    }
    __syncthreads();
#pragma unroll
    for (int u = 0; u < 6; ++u){
        int idx = tid + u*256;           // 0..1535
        int t = idx >> 6, nl = idx & 63;
        float acc = 0.0f;
#pragma unroll
        for (int i = 0; i < TT; ++i)
            acc += s1[i*66 + nl] * sw[t*48 + 2*i] + s1[i*66 + nl+2] * sw[t*48 + 2*i+1];
        sf2[t][nl] = pack2(acc);
    }
    __syncthreads();                     // phase1 reads done -> pool reusable

    // ---- phase 2: pipeline w tiles through pool (2 x 16 KB) ----
    const int th = tid >> 7;             // t-half 0..1
    const int cq = tid & 127;            // c-quad
    const int row4 = tid >> 7;           // staging: not used; map below
    ull acc[12][2];
#pragma unroll
    for (int tt = 0; tt < 12; ++tt){ acc[tt][0] = 0ull; acc[tt][1] = 0ull; }

    // staging map: idx = tid + u*256 in [0,1024): row = idx>>7 (0..7), c4 = idx&127
    const float* wchunk = w + (size_t)n0*CC;

    // stage tile 0
#pragma unroll
    for (int u = 0; u < 4; ++u){
        int idx = tid + u*256;
        int rw = idx >> 7, c4 = idx & 127;
        unsigned sa = (unsigned)__cvta_generic_to_shared(&pool[rw*512 + c4*4]);
        asm volatile("cp.async.cg.shared.global [%0], [%1], 16;"
                     :: "r"(sa), "l"(wchunk + (size_t)rw*CC + c4*4) : "memory");
    }
    asm volatile("cp.async.commit_group;" ::: "memory");

    for (int r = 0; r < 8; ++r){
        const float* cur = (r & 1) ? (pool + 4096) : pool;
        if (r < 7){
            float* nxt = (r & 1) ? pool : (pool + 4096);
#pragma unroll
            for (int u = 0; u < 4; ++u){
                int idx = tid + u*256;
                int rw = idx >> 7, c4 = idx & 127;
                unsigned sa = (unsigned)__cvta_generic_to_shared(&nxt[rw*512 + c4*4]);
                asm volatile("cp.async.cg.shared.global [%0], [%1], 16;"
                             :: "r"(sa), "l"(wchunk + (size_t)((r+1)*8 + rw)*CC + c4*4) : "memory");
            }
            asm volatile("cp.async.commit_group;" ::: "memory");
            asm volatile("cp.async.wait_group 1;" ::: "memory");
        } else {
            asm volatile("cp.async.wait_group 0;" ::: "memory");
        }
        __syncthreads();                 // tile r visible to all
#pragma unroll
        for (int q = 0; q < 8; ++q){
            const ulonglong2 wp = *reinterpret_cast<const ulonglong2*>(&cur[q*512 + 4*cq]);
            const int nl = r*8 + q;
#pragma unroll
            for (int tt = 0; tt < 12; ++tt){
                ull fv = sf2[th*12 + tt][nl];    // LDS.64 broadcast
                acc[tt][0] = fma2(fv, wp.x, acc[tt][0]);
                acc[tt][1] = fma2(fv, wp.y, acc[tt][1]);
            }
        }
        __syncthreads();                 // compute done before next overwrite
    }

#pragma unroll
    for (int tt = 0; tt < 12; ++tt){
        float2 a = unpk2(acc[tt][0]), d = unpk2(acc[tt][1]);
        float* gp = &g_g[((size_t)b*TT + th*12 + tt)*CC + 4*cq];
        asm volatile("red.global.add.v4.f32 [%0], {%1,%2,%3,%4};"
                     :: "l"(gp), "f"(a.x), "f"(a.y), "f"(d.x), "f"(d.y) : "memory");
    }
}

// ---------------- K2d1: s[b,j,k] = sigmoid(g[b,j,:] . f2cT[b,k,:] + bias) ----------------
__global__ void __launch_bounds__(128) k2d1_attn(const float* __restrict__ bbias){
    const int b = blockIdx.x / 24;
    const int jj = blockIdx.x % 24;
    const int tid  = threadIdx.x;
    const int wrp  = tid >> 5;
    const int lane = tid & 31;
    __shared__ __align__(16) float sg[CC];
    const float* grow = g_g + ((size_t)b*TT + jj)*CC;
#pragma unroll
    for (int u = 0; u < 4; ++u) sg[tid + u*128] = grow[tid + u*128];
    __syncthreads();
    const ull* sg2 = reinterpret_cast<const ull*>(sg);
    const ull* f0  = reinterpret_cast<const ull*>(g_f2cT + ((size_t)b*TT + wrp*6)*CC);
    ull acc[6] = {0ull,0ull,0ull,0ull,0ull,0ull};
#pragma unroll
    for (int it = 0; it < 8; ++it){
        ull gv = sg2[lane + it*32];
#pragma unroll
        for (int kk = 0; kk < 6; ++kk)
            acc[kk] = fma2(f0[(size_t)kk*256 + lane + it*32], gv, acc[kk]);
    }
#pragma unroll
    for (int kk = 0; kk < 6; ++kk)
#pragma unroll
        for (int off = 16; off > 0; off >>= 1)
            acc[kk] = add2(acc[kk], __shfl_xor_sync(0xffffffffu, acc[kk], off));
    if (lane < 6){
        int k = wrp*6 + lane;
        float2 aa = unpk2(acc[lane]);
        float sv = aa.x + aa.y + bbias[jj*TT + k];
        g_s[((size_t)b*TT + jj)*TT + k] = 1.0f/(1.0f + __expf(-sv));
    }
}

// ---------------- K2d2: l = v @ s; BN + mask + softmax (single block) ----------------
__global__ void k2d2_final(const float* __restrict__ v, const float* __restrict__ gamma,
                           const float* __restrict__ beta, float* __restrict__ out){
    const int tid = threadIdx.x;
    __shared__ float ss[BB][TT][TT];
    __shared__ float sv[TT][TT];
    __shared__ float sl[192][25];
    __shared__ float smean[TT], sinv[TT];
    for (int idx = tid; idx < BB*TT*TT; idx += 192) ((float*)ss)[idx] = g_s[idx];
    for (int idx = tid; idx < TT*TT;   idx += 192) ((float*)sv)[idx] = v[idx];
    __syncthreads();
    const int b = tid / TT, i = tid % TT;
    float l[TT];
#pragma unroll
    for (int k = 0; k < TT; ++k) l[k] = 0.0f;
#pragma unroll
    for (int jj = 0; jj < TT; ++jj){
        float vij = sv[i][jj];
#pragma unroll
        for (int k = 0; k < TT; ++k) l[k] = fmaf(vij, ss[b][jj][k], l[k]);
    }
#pragma unroll
    for (int k = 0; k < TT; ++k) sl[tid][k] = l[k];
    __syncthreads();
    if (tid < TT){
        float s = 0.0f, s2 = 0.0f;
        for (int r = 0; r < 192; ++r){ float x = sl[r][tid]; s += x; s2 = fmaf(x, x, s2); }
        float m = s * (1.0f/192.0f);
        smean[tid] = m;
        sinv[tid]  = rsqrtf(s2 * (1.0f/192.0f) - m*m + 1e-5f);
    }
    __syncthreads();
    float mx = -3.4e38f;
#pragma unroll
    for (int k = 0; k < TT; ++k){
        float y = (l[k] - smean[k]) * sinv[k] * gamma[k] + beta[k];
        if ((i < 12) != (k < 12)) y -= 1e13f;
        l[k] = y;
        mx = fmaxf(mx, y);
    }
    float s = 0.0f;
#pragma unroll
    for (int k = 0; k < TT; ++k){ float e = __expf(l[k] - mx); l[k] = e; s += e; }
    float inv = 1.0f / s;
#pragma unroll
    for (int k = 0; k < TT; ++k)
        out[((size_t)b*TT + i)*TT + k] = l[k] * inv;
}

// ---------------- launch ----------------
extern "C" void kernel_launch(void* const* d_in, const int* in_sizes, int n_in,
                              void* d_out, int out_size){
    const float* seq   = (const float*)d_in[0];
    const float* w1    = (const float*)d_in[1];
    const float* w2    = (const float*)d_in[2];
    const float* Wd1   = (const float*)d_in[3];
    const float* Wd2   = (const float*)d_in[4];
    const float* w     = (const float*)d_in[5];
    const float* bbias = (const float*)d_in[6];
    const float* v     = (const float*)d_in[7];
    const float* gamma = (const float*)d_in[8];
    const float* beta  = (const float*)d_in[9];
    float* out = (float*)d_out;

    cudaFuncSetAttribute(k1_reduce, cudaFuncAttributeMaxDynamicSharedMemorySize, K1_SMEM);
    cudaFuncSetAttribute(k2b_conv2, cudaFuncAttributeMaxDynamicSharedMemorySize, K2B_SMEM);

    // order: 4th launch (k2ac_fused) is the ncu capture slot
    k0_zero   <<<(BB*TT*NNODES + 255)/256, 256>>>();
    k1_reduce <<<1024, 192, K1_SMEM>>>(seq, w1, w2);
    k2b_conv2 <<<128, 256, K2B_SMEM>>>(Wd2);
    k2ac_fused<<<256, 256>>>(Wd1, w);
    k2d1_attn <<<BB*TT, 128>>>(bbias);
    k2d2_final<<<1, 192>>>(v, gamma, beta, out);
}